// round 12
// baseline (speedup 1.0000x reference)
#include <cuda_runtime.h>

#define CA_EPS  1e-8f
#define CA_K    512
#define CA_FF   16          // F*F
#define CA_HALF 8192        // K*FF : x-flat size per batch / xc-half offset in W row
#define CA_FEAT 16384       // 2*K*FF : W row length
#define SLICE   32
#define NT      512
#define GRID    32
#define NTICKETS (8 * GRID) // 8 ticket-bearing warps per CTA

__device__ float4   g_accum;      // zero at entry; restored to zero every call
__device__ unsigned g_count;      // zero at entry; restored to zero every call

// grid = 32 (16 slice-CTAs per batch), block = 512 (one thread per channel).
//
// Algebraic collapse (p = 1.0): the [B,512,512,256] einsum intermediate in the
// reference cancels out of the STE comparison entirely —
//   num(m,n) = S2[m]S2[n] + 2e S1[m]S1[n] + 256e^2,  den(m,n) = S1[m]S1[n] + 256e
// are symmetric in (m,n), so cm[m,n] > cm[n,m]  <=>  D[m] > D[n] where
// D[k] = (sum(xh+e)^2 + e)/(sum(xh+e) + e) + e over the channel's 16 values
// (xh = x / (batch_max + e)). mul_factor[k] = relu(wins[k] - losses[k]) is a
// pure rank statistic of D; the output is bias + x . (W_x + fac*W_xc).
__global__ __launch_bounds__(NT, 1)
void ca_fused(const float* __restrict__ x, const float* __restrict__ W,
              const float* __restrict__ bias, float* __restrict__ out) {
    const int b    = blockIdx.x >> 4;            // batch (0..1)
    const int c0   = (blockIdx.x & 15) * SLICE;  // slice start channel
    const int tid  = threadIdx.x;
    const int lane = tid & 31, warp = tid >> 5;

    __shared__ unsigned s_red[16];
    __shared__ float s_D[CA_K];
    __shared__ float s_fac[SLICE];

    // ---- FIRST in the L1tex queue: own-channel x loads (gate phase 1) ------
    // L1tex completion order == issue order; these feed the max reduction that
    // everything else chains behind, so they must issue before the prefetches.
    const float4* xp = reinterpret_cast<const float4*>(x + (size_t)b * CA_HALF) + (size_t)tid * 4;
    float4 a0 = xp[0], a1 = xp[1], a2 = xp[2], a3 = xp[3];

    // ---- prefetch matvec operands (threads 0..255), all LDG.128 ------------
    // Not consumed until phase 4; latency fully hidden behind phases 1-3.
    float4 wa = make_float4(0.f, 0.f, 0.f, 0.f);
    float4 wb = wa, xu = wa;
    int ch_l = 0;
    if (tid < 256) {
        const int cls = tid >> 7;                // warps 0-3 -> class0; 4-7 -> class1
        const int u   = tid & 127;
        ch_l = u >> 2;
        const int v = u & 3;
        const float* wbase = W + (size_t)cls * CA_FEAT + (size_t)(c0 + ch_l) * CA_FF + v * 4;
        wa = *reinterpret_cast<const float4*>(wbase);
        wb = *reinterpret_cast<const float4*>(wbase + CA_HALF);
        xu = *reinterpret_cast<const float4*>(x + (size_t)b * CA_HALF + (size_t)(c0 + ch_l) * CA_FF + v * 4);
    }

    // ---- LAST: bias (consumed only by the finalizer at kernel end) ---------
    float bias0 = 0.f, bias1 = 0.f;
    if (lane == 0 && warp < 8) { bias0 = __ldg(bias); bias1 = __ldg(bias + 1); }

    // ---- phase 1: per-batch global max (x >= 0 -> uint max == float max) ---
    float m = fmaxf(fmaxf(fmaxf(a0.x, a0.y), fmaxf(a0.z, a0.w)),
                    fmaxf(fmaxf(a1.x, a1.y), fmaxf(a1.z, a1.w)));
    m = fmaxf(m, fmaxf(fmaxf(fmaxf(a2.x, a2.y), fmaxf(a2.z, a2.w)),
                       fmaxf(fmaxf(a3.x, a3.y), fmaxf(a3.z, a3.w))));
    unsigned mu = __reduce_max_sync(0xFFFFFFFFu, __float_as_uint(m));
    if (lane == 0) s_red[warp] = mu;
    __syncthreads();
    unsigned mmu = __reduce_max_sync(0xFFFFFFFFu, s_red[lane & 15]);
    const float inv = 1.0f / (__uint_as_float(mmu) + CA_EPS);

    // ---- phase 2: lehmer_den D for the own channel -------------------------
    {
        float s1 = 0.f, s2 = 0.f, t;
        t = a0.x * inv + CA_EPS; s1 += t; s2 += t * t;
        t = a0.y * inv + CA_EPS; s1 += t; s2 += t * t;
        t = a0.z * inv + CA_EPS; s1 += t; s2 += t * t;
        t = a0.w * inv + CA_EPS; s1 += t; s2 += t * t;
        t = a1.x * inv + CA_EPS; s1 += t; s2 += t * t;
        t = a1.y * inv + CA_EPS; s1 += t; s2 += t * t;
        t = a1.z * inv + CA_EPS; s1 += t; s2 += t * t;
        t = a1.w * inv + CA_EPS; s1 += t; s2 += t * t;
        t = a2.x * inv + CA_EPS; s1 += t; s2 += t * t;
        t = a2.y * inv + CA_EPS; s1 += t; s2 += t * t;
        t = a2.z * inv + CA_EPS; s1 += t; s2 += t * t;
        t = a2.w * inv + CA_EPS; s1 += t; s2 += t * t;
        t = a3.x * inv + CA_EPS; s1 += t; s2 += t * t;
        t = a3.y * inv + CA_EPS; s1 += t; s2 += t * t;
        t = a3.z * inv + CA_EPS; s1 += t; s2 += t * t;
        t = a3.w * inv + CA_EPS; s1 += t; s2 += t * t;
        s_D[tid] = (s2 + CA_EPS) / (s1 + CA_EPS) + CA_EPS;
    }
    __syncthreads();

    // ---- phase 3: warp w handles slice channels c0+2w, c0+2w+1 -------------
    // bool[m,n] decision reduces to sign(D[m]-D[n]); fac = relu(wins-losses).
    {
        const float Dk0 = s_D[c0 + 2 * warp];       // broadcast reads
        const float Dk1 = s_D[c0 + 2 * warp + 1];
        int wl0 = 0, wl1 = 0;
        #pragma unroll
        for (int i = 0; i < 16; ++i) {              // conflict-free, shared loads
            float d = s_D[i * 32 + lane];
            wl0 += (Dk0 > d) - (d > Dk0);
            wl1 += (Dk1 > d) - (d > Dk1);
        }
        wl0 = __reduce_add_sync(0xFFFFFFFFu, wl0);
        wl1 = __reduce_add_sync(0xFFFFFFFFu, wl1);
        if (lane == 0) {
            s_fac[2 * warp]     = fmaxf((float)wl0, 0.0f);
            s_fac[2 * warp + 1] = fmaxf((float)wl1, 0.0f);
        }
    }
    __syncthreads();

    // ---- phase 4: slice matvec partial -> per-warp RED + self-ticket -------
    if (tid < 256) {
        const float f = s_fac[ch_l];
        float part;
        part  = xu.x * fmaf(f, wb.x, wa.x);
        part += xu.y * fmaf(f, wb.y, wa.y);
        part += xu.z * fmaf(f, wb.z, wa.z);
        part += xu.w * fmaf(f, wb.w, wa.w);
        #pragma unroll
        for (int off = 16; off > 0; off >>= 1)
            part += __shfl_xor_sync(0xFFFFFFFFu, part, off);

        if (lane == 0) {
            const int cls = tid >> 7;
            float* acc = reinterpret_cast<float*>(&g_accum);
            atomicAdd(acc + (b * 2 + cls), part);   // REDG, no return
            // acq_rel ticket from the SAME thread: cumulative release orders
            // the RED above without MEMBAR.GPU/CCTL. Finalizer = 256th arrival.
            unsigned ticket;
            asm volatile("atom.acq_rel.gpu.global.add.u32 %0, [%1], 1;"
                         : "=r"(ticket) : "l"(&g_count) : "memory");
            if (ticket == NTICKETS - 1) {
                // all tickets in => all REDs visible at L2
                float4 r;
                asm volatile("ld.global.cg.v4.f32 {%0,%1,%2,%3}, [%4];"
                             : "=f"(r.x), "=f"(r.y), "=f"(r.z), "=f"(r.w)
                             : "l"(&g_accum) : "memory");
                float4 res = make_float4(bias0 + r.x, bias1 + r.y,
                                         bias0 + r.z, bias1 + r.w);
                *reinterpret_cast<float4*>(out) = res;
                asm volatile("st.global.cg.v4.f32 [%0], {%1,%2,%3,%4};"
                             :: "l"(&g_accum), "f"(0.f), "f"(0.f), "f"(0.f), "f"(0.f)
                             : "memory");
                __stcg(&g_count, 0u);
            }
        }
    }
}

extern "C" void kernel_launch(void* const* d_in, const int* in_sizes, int n_in,
                              void* d_out, int out_size) {
    const float* x    = (const float*)d_in[0];   // [2, 512, 4, 4]
    const float* W    = (const float*)d_in[1];   // [2, 16384]
    const float* bias = (const float*)d_in[2];   // [2]
    float* out = (float*)d_out;                  // [2, 2]
    ca_fused<<<GRID, NT>>>(x, W, bias, out);
}

// round 13
// speedup vs baseline: 1.0037x; 1.0037x over previous
#include <cuda_runtime.h>

#define CA_EPS  1e-8f
#define CA_K    512
#define CA_FF   16          // F*F
#define CA_HALF 8192        // K*FF : x-flat size per batch / xc-half offset in W row
#define CA_FEAT 16384       // 2*K*FF : W row length
#define SLICE   32
#define NT      512
#define GRID    32
#define NTICKETS (8 * GRID) // 8 ticket-bearing warps per CTA

__device__ float4   g_accum;      // zero at entry; restored to zero every call
__device__ unsigned g_count;      // zero at entry; restored to zero every call

// grid = 32 (16 slice-CTAs per batch), block = 512 (one thread per channel).
//
// Algebraic collapse (p = 1.0): the [B,512,512,256] einsum intermediate in the
// reference cancels out of the STE comparison entirely —
//   num(m,n) = S2[m]S2[n] + 2e S1[m]S1[n] + 256e^2,  den(m,n) = S1[m]S1[n] + 256e
// are symmetric in (m,n), so cm[m,n] > cm[n,m]  <=>  D[m] > D[n] where
// D[k] = (sum(xh+e)^2 + e)/(sum(xh+e) + e) + e over the channel's 16 values
// (xh = x / (batch_max + e)). mul_factor[k] = relu(wins[k] - losses[k]) is a
// pure rank statistic of D; the output is bias + x . (W_x + fac*W_xc).
__global__ __launch_bounds__(NT, 1)
void ca_fused(const float* __restrict__ x, const float* __restrict__ W,
              const float* __restrict__ bias, float* __restrict__ out) {
    const int b    = blockIdx.x >> 4;            // batch (0..1)
    const int c0   = (blockIdx.x & 15) * SLICE;  // slice start channel
    const int tid  = threadIdx.x;
    const int lane = tid & 31, warp = tid >> 5;

    __shared__ unsigned s_red[16];
    __shared__ float s_D[CA_K];
    __shared__ float s_fac[SLICE];

    // ---- early prefetch: bias in every potential finalizer -----------------
    float bias0 = 0.f, bias1 = 0.f;
    if (lane == 0 && warp < 8) { bias0 = __ldg(bias); bias1 = __ldg(bias + 1); }

    // ---- prefetch matvec operands (threads 0..255), all LDG.128 ------------
    // cls = tid>>7 (class), u = tid&127 -> ch_l = u>>2 (0..31), v = u&3
    float4 wa = make_float4(0.f, 0.f, 0.f, 0.f);
    float4 wb = wa, xu = wa;
    int ch_l = 0;
    if (tid < 256) {
        const int cls = tid >> 7;                // warps 0-3 -> class0; 4-7 -> class1
        const int u   = tid & 127;
        ch_l = u >> 2;
        const int v = u & 3;
        const float* wbase = W + (size_t)cls * CA_FEAT + (size_t)(c0 + ch_l) * CA_FF + v * 4;
        wa = *reinterpret_cast<const float4*>(wbase);
        wb = *reinterpret_cast<const float4*>(wbase + CA_HALF);
        xu = *reinterpret_cast<const float4*>(x + (size_t)b * CA_HALF + (size_t)(c0 + ch_l) * CA_FF + v * 4);
    }

    // ---- load own channel (k = tid): 4 contiguous float4 -------------------
    const float4* xp = reinterpret_cast<const float4*>(x + (size_t)b * CA_HALF) + (size_t)tid * 4;
    float4 a0 = xp[0], a1 = xp[1], a2 = xp[2], a3 = xp[3];

    // ---- phase 1: per-batch global max (x >= 0 -> uint max == float max) ---
    float m = fmaxf(fmaxf(fmaxf(a0.x, a0.y), fmaxf(a0.z, a0.w)),
                    fmaxf(fmaxf(a1.x, a1.y), fmaxf(a1.z, a1.w)));
    m = fmaxf(m, fmaxf(fmaxf(fmaxf(a2.x, a2.y), fmaxf(a2.z, a2.w)),
                       fmaxf(fmaxf(a3.x, a3.y), fmaxf(a3.z, a3.w))));
    unsigned mu = __reduce_max_sync(0xFFFFFFFFu, __float_as_uint(m));
    if (lane == 0) s_red[warp] = mu;
    __syncthreads();
    unsigned mmu = __reduce_max_sync(0xFFFFFFFFu, s_red[lane & 15]);
    const float inv = 1.0f / (__uint_as_float(mmu) + CA_EPS);

    // ---- phase 2: lehmer_den D for the own channel -------------------------
    {
        float s1 = 0.f, s2 = 0.f, t;
        t = a0.x * inv + CA_EPS; s1 += t; s2 += t * t;
        t = a0.y * inv + CA_EPS; s1 += t; s2 += t * t;
        t = a0.z * inv + CA_EPS; s1 += t; s2 += t * t;
        t = a0.w * inv + CA_EPS; s1 += t; s2 += t * t;
        t = a1.x * inv + CA_EPS; s1 += t; s2 += t * t;
        t = a1.y * inv + CA_EPS; s1 += t; s2 += t * t;
        t = a1.z * inv + CA_EPS; s1 += t; s2 += t * t;
        t = a1.w * inv + CA_EPS; s1 += t; s2 += t * t;
        t = a2.x * inv + CA_EPS; s1 += t; s2 += t * t;
        t = a2.y * inv + CA_EPS; s1 += t; s2 += t * t;
        t = a2.z * inv + CA_EPS; s1 += t; s2 += t * t;
        t = a2.w * inv + CA_EPS; s1 += t; s2 += t * t;
        t = a3.x * inv + CA_EPS; s1 += t; s2 += t * t;
        t = a3.y * inv + CA_EPS; s1 += t; s2 += t * t;
        t = a3.z * inv + CA_EPS; s1 += t; s2 += t * t;
        t = a3.w * inv + CA_EPS; s1 += t; s2 += t * t;
        s_D[tid] = (s2 + CA_EPS) / (s1 + CA_EPS) + CA_EPS;
    }
    __syncthreads();

    // ---- phase 3: warp w handles slice channels c0+2w, c0+2w+1 -------------
    // bool[m,n] decision reduces to sign(D[m]-D[n]); fac = relu(wins-losses).
    {
        const float Dk0 = s_D[c0 + 2 * warp];       // broadcast reads
        const float Dk1 = s_D[c0 + 2 * warp + 1];
        int wl0 = 0, wl1 = 0;
        #pragma unroll
        for (int i = 0; i < 16; ++i) {              // conflict-free, shared loads
            float d = s_D[i * 32 + lane];
            wl0 += (Dk0 > d) - (d > Dk0);
            wl1 += (Dk1 > d) - (d > Dk1);
        }
        wl0 = __reduce_add_sync(0xFFFFFFFFu, wl0);
        wl1 = __reduce_add_sync(0xFFFFFFFFu, wl1);
        if (lane == 0) {
            s_fac[2 * warp]     = fmaxf((float)wl0, 0.0f);
            s_fac[2 * warp + 1] = fmaxf((float)wl1, 0.0f);
        }
    }
    __syncthreads();

    // ---- phase 4: slice matvec partial -> per-warp RED + self-ticket -------
    if (tid < 256) {
        const float f = s_fac[ch_l];
        float part;
        part  = xu.x * fmaf(f, wb.x, wa.x);
        part += xu.y * fmaf(f, wb.y, wa.y);
        part += xu.z * fmaf(f, wb.z, wa.z);
        part += xu.w * fmaf(f, wb.w, wa.w);
        #pragma unroll
        for (int off = 16; off > 0; off >>= 1)
            part += __shfl_xor_sync(0xFFFFFFFFu, part, off);

        if (lane == 0) {
            const int cls = tid >> 7;
            float* acc = reinterpret_cast<float*>(&g_accum);
            atomicAdd(acc + (b * 2 + cls), part);   // REDG, no return
            // acq_rel ticket from the SAME thread: cumulative release orders
            // the RED above without MEMBAR.GPU/CCTL. Finalizer = 256th arrival.
            unsigned ticket;
            asm volatile("atom.acq_rel.gpu.global.add.u32 %0, [%1], 1;"
                         : "=r"(ticket) : "l"(&g_count) : "memory");
            if (ticket == NTICKETS - 1) {
                // all tickets in => all REDs visible at L2
                float4 r;
                asm volatile("ld.global.cg.v4.f32 {%0,%1,%2,%3}, [%4];"
                             : "=f"(r.x), "=f"(r.y), "=f"(r.z), "=f"(r.w)
                             : "l"(&g_accum) : "memory");
                float4 res = make_float4(bias0 + r.x, bias1 + r.y,
                                         bias0 + r.z, bias1 + r.w);
                *reinterpret_cast<float4*>(out) = res;
                asm volatile("st.global.cg.v4.f32 [%0], {%1,%2,%3,%4};"
                             :: "l"(&g_accum), "f"(0.f), "f"(0.f), "f"(0.f), "f"(0.f)
                             : "memory");
                __stcg(&g_count, 0u);
            }
        }
    }
}

extern "C" void kernel_launch(void* const* d_in, const int* in_sizes, int n_in,
                              void* d_out, int out_size) {
    const float* x    = (const float*)d_in[0];   // [2, 512, 4, 4]
    const float* W    = (const float*)d_in[1];   // [2, 16384]
    const float* bias = (const float*)d_in[2];   // [2]
    float* out = (float*)d_out;                  // [2, 2]
    ca_fused<<<GRID, NT>>>(x, W, bias, out);
}